// round 16
// baseline (speedup 1.0000x reference)
#include <cuda_runtime.h>
#include <cuda_fp16.h>
#include <cstdint>

// ---------------------------------------------------------------------------
// Problem constants
// ---------------------------------------------------------------------------
namespace {
constexpr int T_STEPS = 128, BATCH = 512, HID = 512, INP = 512;
constexpr int M_TOT = T_STEPS * BATCH;              // 65536 rows
constexpr long long BH = (long long)BATCH * HID;    // 262144 sequences

// Fused kernel: CTA = one batch b; 4 h-tiles of 128; BK=16; GEMM warp tile 64x32
constexpr int BN = 128, BK = 16;
constexpr int CHUNKS = INP / BK;                    // 32
constexpr int NTILES = HID / BN;                    // 4
constexpr int NTH = 512;
constexpr int PITCH  = 48;                          // 32B data + 16B pad (bank-clean)
constexpr int A_T    = 128 * PITCH;                 // 6144 per A split
constexpr int B_T    = BN * PITCH;                  // 6144 per B split
constexpr int OFF_AH = 0;
constexpr int OFF_AM = A_T;
constexpr int OFF_BH = 2 * A_T;
constexpr int OFF_BM = 3 * A_T;
constexpr int STAGE_B = 4 * A_T;                    // 24576
constexpr int NSTAGE = 3;                           // slots mod 3
constexpr int PIPE_B = NSTAGE * STAGE_B;            // 73728
// two xp ping-pong buffers AFTER the pipeline region (no overlay!)
constexpr int XP = 132;                             // fp32 words per row
constexpr int XP_TILE_B = 128 * XP * 4;             // 67584
constexpr int XP0 = PIPE_B;                         // 73728
constexpr int SMEM_TOTAL = PIPE_B + 2 * XP_TILE_B;  // 208896 <= ~227KB
// split grid partition (R9-proven)
constexpr int XBLK = 4096;
constexpr int WBLK = 32;
}

// Static scratch (allowed; no allocs)
__device__ __half g_xh[(size_t)M_TOT * INP];        // x hi split, [B][T][K]
__device__ __half g_xm[(size_t)M_TOT * INP];        // x mid split
__device__ __half g_wh[(size_t)HID * INP];          // [H][K]
__device__ __half g_wm[(size_t)HID * INP];

// ---------------------------------------------------------------------------
// PTX helpers
// ---------------------------------------------------------------------------
__device__ __forceinline__ uint32_t smem_u32(const void* p) {
    uint32_t a;
    asm("{ .reg .u64 t; cvta.to.shared.u64 t, %1; cvt.u32.u64 %0, t; }"
        : "=r"(a) : "l"(p));
    return a;
}
__device__ __forceinline__ void ldsm_x4(uint32_t* r, uint32_t addr) {
    asm volatile("ldmatrix.sync.aligned.m8n8.x4.shared.b16 {%0,%1,%2,%3}, [%4];"
                 : "=r"(r[0]), "=r"(r[1]), "=r"(r[2]), "=r"(r[3]) : "r"(addr));
}
__device__ __forceinline__ void mma_f16(float* c, const uint32_t* a,
                                        const uint32_t* b) {
    asm volatile(
        "mma.sync.aligned.m16n8k16.row.col.f32.f16.f16.f32 "
        "{%0,%1,%2,%3}, {%4,%5,%6,%7}, {%8,%9}, {%0,%1,%2,%3};"
        : "+f"(c[0]), "+f"(c[1]), "+f"(c[2]), "+f"(c[3])
        : "r"(a[0]), "r"(a[1]), "r"(a[2]), "r"(a[3]), "r"(b[0]), "r"(b[1]));
}
__device__ __forceinline__ void cp16(uint32_t dst, const void* src) {
    asm volatile("cp.async.cg.shared.global [%0], [%1], 16;"
                 :: "r"(dst), "l"(src) : "memory");
}
__device__ __forceinline__ void cp_commit() {
    asm volatile("cp.async.commit_group;" ::: "memory");
}
__device__ __forceinline__ void cp_wait1() {
    asm volatile("cp.async.wait_group 1;" ::: "memory");
}
__device__ __forceinline__ void bar_gemm() {        // GEMM warps only (256 thr)
    asm volatile("bar.sync 1, 256;" ::: "memory");
}
__device__ __forceinline__ uint32_t hpack(__half a, __half b) {
    __half2 t(a, b);
    return *reinterpret_cast<uint32_t*>(&t);
}

// ---------------------------------------------------------------------------
// Merged split pass (R9-proven): 8 float4 per thread.
// ---------------------------------------------------------------------------
__global__ __launch_bounds__(256)
void split_kernel(const float4* __restrict__ x, const float4* __restrict__ W)
{
    __half hh[4], mm[4];
    if (blockIdx.x < XBLK) {
        const long long gid  = (long long)blockIdx.x * blockDim.x + threadIdx.x;
        const long long flat = gid * 32;
        const int k0 = (int)(flat & 511);
        const int b  = (int)((flat >> 9) & 511);
        const int t  = (int)(flat >> 18);
        const long long dflat = (((long long)b * T_STEPS + t) << 9) | k0;

        float4 v[8];
        #pragma unroll
        for (int g = 0; g < 8; ++g) v[g] = x[flat / 4 + g];

        uint32_t hp[16], mp[16];
        #pragma unroll
        for (int g = 0; g < 8; ++g) {
            const float f[4] = {v[g].x, v[g].y, v[g].z, v[g].w};
            #pragma unroll
            for (int j = 0; j < 4; ++j) {
                hh[j] = __float2half_rn(f[j]);
                mm[j] = __float2half_rn(f[j] - __half2float(hh[j]));
            }
            hp[g * 2 + 0] = hpack(hh[0], hh[1]); hp[g * 2 + 1] = hpack(hh[2], hh[3]);
            mp[g * 2 + 0] = hpack(mm[0], mm[1]); mp[g * 2 + 1] = hpack(mm[2], mm[3]);
        }
        uint4* hd = (uint4*)g_xh;
        uint4* md = (uint4*)g_xm;
        const long long o = dflat / 8;
        #pragma unroll
        for (int g = 0; g < 4; ++g) {
            hd[o + g] = make_uint4(hp[4 * g], hp[4 * g + 1], hp[4 * g + 2], hp[4 * g + 3]);
            md[o + g] = make_uint4(mp[4 * g], mp[4 * g + 1], mp[4 * g + 2], mp[4 * g + 3]);
        }
    } else {
        const int i = (((int)blockIdx.x - XBLK) * 256 + (int)threadIdx.x) * 8;
        float4 v[8];
        #pragma unroll
        for (int g = 0; g < 8; ++g) v[g] = W[i + g];
        uint32_t hp[16], mp[16];
        #pragma unroll
        for (int g = 0; g < 8; ++g) {
            const float f[4] = {v[g].x, v[g].y, v[g].z, v[g].w};
            #pragma unroll
            for (int j = 0; j < 4; ++j) {
                hh[j] = __float2half_rn(f[j]);
                mm[j] = __float2half_rn(f[j] - __half2float(hh[j]));
            }
            hp[g * 2 + 0] = hpack(hh[0], hh[1]); hp[g * 2 + 1] = hpack(hh[2], hh[3]);
            mp[g * 2 + 0] = hpack(mm[0], mm[1]); mp[g * 2 + 1] = hpack(mm[2], mm[3]);
        }
        uint4* hd = (uint4*)g_wh;
        uint4* md = (uint4*)g_wm;
        const int o = i / 2;
        #pragma unroll
        for (int g = 0; g < 4; ++g) {
            hd[o + g] = make_uint4(hp[4 * g], hp[4 * g + 1], hp[4 * g + 2], hp[4 * g + 3]);
            md[o + g] = make_uint4(mp[4 * g], mp[4 * g + 1], mp[4 * g + 2], mp[4 * g + 3]);
        }
    }
}

// ---------------------------------------------------------------------------
// FUSED pipelined kernel. CTA = batch b (grid 512), 512 threads:
//   warps 0-7 : GEMM engine, tile i -> xp buffer (i&1)
//   warps 8-11: LIF scan engine, tile i-1 from xp buffer ((i-1)&1)
//   one __syncthreads per tile handoff; GEMM-internal sync = bar.sync 1,256.
// ---------------------------------------------------------------------------
__global__ __launch_bounds__(NTH, 1)
void fused_kernel(const float* __restrict__ bias,
                  float* __restrict__ out, float* __restrict__ states)
{
    extern __shared__ char smem[];
    const uint32_t sbase = smem_u32(smem);
    const int tid = threadIdx.x;
    const int wid = tid >> 5;
    const int lid = tid & 31;
    const int b = blockIdx.x;
    const bool gemm_role = (tid < 256);

    const __half* Ah = g_xh + (size_t)b * T_STEPS * INP;
    const __half* Am = g_xm + (size_t)b * T_STEPS * INP;

    // GEMM addressing
    const int warp_m = wid & 1;          // 64-row (t) half
    const int warp_n = wid >> 1;         // 32-col slice (0..3 for wid 0..7)
    const int quad = lid >> 3, lrow = lid & 7;
    const uint32_t laneA = (uint32_t)(((quad & 1) * 8 + lrow) * PITCH + (quad >> 1) * 16);
    const uint32_t laneB = (uint32_t)(((quad >> 1) * 8 + lrow) * PITCH + (quad & 1) * 16);

    // stage fill (GEMM warps only): 1024 cp16, 4/thread
    auto issue_stage = [&](int c, int n0) {
        const int kt = c * BK;
        const uint32_t sdst = sbase + (uint32_t)((c % NSTAGE) * STAGE_B);
        #pragma unroll
        for (int i = 0; i < 4; ++i) {
            const int q    = i * 256 + tid;
            const int tile = q >> 8;            // 0:Ah 1:Am 2:Bh 3:Bm
            const int t    = q & 255;
            const int row  = t >> 1;
            const int cc   = t & 1;
            const __half* src;
            if      (tile == 0) src = Ah   + (size_t)row * INP + kt + cc * 8;
            else if (tile == 1) src = Am   + (size_t)row * INP + kt + cc * 8;
            else if (tile == 2) src = g_wh + (size_t)(n0 + row) * INP + kt + cc * 8;
            else                src = g_wm + (size_t)(n0 + row) * INP + kt + cc * 8;
            cp16(sdst + (uint32_t)(tile * A_T + row * PITCH + cc * 16), src);
        }
        cp_commit();
    };

    for (int tile = 0; tile <= NTILES; ++tile) {
        if (tile < NTILES && gemm_role) {
            // ================= GEMM of tile `tile` =================
            const int n0 = tile * BN;
            float acc[4][4][4];
            #pragma unroll
            for (int i = 0; i < 4; ++i)
                #pragma unroll
                for (int j = 0; j < 4; ++j)
                    #pragma unroll
                    for (int k = 0; k < 4; ++k) acc[i][j][k] = 0.f;

            issue_stage(0, n0);
            issue_stage(1, n0);

            for (int c = 0; c < CHUNKS; ++c) {
                cp_wait1();
                bar_gemm();

                const uint32_t stg = sbase + (uint32_t)((c % NSTAGE) * STAGE_B);
                const uint32_t aB  = stg + (uint32_t)(warp_m * 64 * PITCH) + laneA;
                const uint32_t bB  = stg + (uint32_t)(warp_n * 32 * PITCH) + laneB;

                uint32_t afr[4][4], bfh[4][2], bfm[4][2];

                // B-hi (2 ldsm) + A-hi (4 ldsm)
                #pragma unroll
                for (int bp = 0; bp < 2; ++bp) {
                    uint32_t r4[4];
                    ldsm_x4(r4, bB + (uint32_t)(OFF_BH + bp * 16 * PITCH));
                    bfh[bp * 2 + 0][0] = r4[0]; bfh[bp * 2 + 0][1] = r4[1];
                    bfh[bp * 2 + 1][0] = r4[2]; bfh[bp * 2 + 1][1] = r4[3];
                }
                #pragma unroll
                for (int mt = 0; mt < 4; ++mt)
                    ldsm_x4(afr[mt], aB + (uint32_t)(OFF_AH + mt * 16 * PITCH));

                if (c + 2 < CHUNKS) issue_stage(c + 2, n0);
                else                cp_commit();

                // hh
                #pragma unroll
                for (int mt = 0; mt < 4; ++mt)
                    #pragma unroll
                    for (int nt = 0; nt < 4; ++nt)
                        mma_f16(acc[mt][nt], afr[mt], bfh[nt]);

                // B-mid under hh shadow, then hm
                #pragma unroll
                for (int bp = 0; bp < 2; ++bp) {
                    uint32_t r4[4];
                    ldsm_x4(r4, bB + (uint32_t)(OFF_BM + bp * 16 * PITCH));
                    bfm[bp * 2 + 0][0] = r4[0]; bfm[bp * 2 + 0][1] = r4[1];
                    bfm[bp * 2 + 1][0] = r4[2]; bfm[bp * 2 + 1][1] = r4[3];
                }
                #pragma unroll
                for (int mt = 0; mt < 4; ++mt)
                    #pragma unroll
                    for (int nt = 0; nt < 4; ++nt)
                        mma_f16(acc[mt][nt], afr[mt], bfm[nt]);

                // A-mid, then mh
                #pragma unroll
                for (int mt = 0; mt < 4; ++mt)
                    ldsm_x4(afr[mt], aB + (uint32_t)(OFF_AM + mt * 16 * PITCH));
                #pragma unroll
                for (int mt = 0; mt < 4; ++mt)
                    #pragma unroll
                    for (int nt = 0; nt < 4; ++nt)
                        mma_f16(acc[mt][nt], afr[mt], bfh[nt]);
            }

            // epilogue: acc -> xp buffer (tile & 1)
            float* xs = (float*)(smem + XP0 + (tile & 1) * XP_TILE_B);
            const int tr = lid >> 2;
            const int tc = (lid & 3) * 2;
            #pragma unroll
            for (int nt = 0; nt < 4; ++nt) {
                const int col = warp_n * 32 + nt * 8 + tc;
                #pragma unroll
                for (int mt = 0; mt < 4; ++mt) {
                    const int row = warp_m * 64 + mt * 16 + tr;
                    *(float2*)&xs[row * XP + col] =
                        make_float2(acc[mt][nt][0], acc[mt][nt][1]);
                    *(float2*)&xs[(row + 8) * XP + col] =
                        make_float2(acc[mt][nt][2], acc[mt][nt][3]);
                }
            }
        }

        if (tile >= 1 && !gemm_role && (tid - 256) < 128) {
            // ================= LIF scan of tile `tile-1` =================
            const int st = tid - 256;                // 0..127
            const int jt = tile - 1;
            const int h  = jt * BN + st;
            const float bias_h = bias[h];
            const float* xs = (const float*)(smem + XP0 + (jt & 1) * XP_TILE_B);

            float v[4]  = {0.f, 0.f, 0.f, 0.f};
            float av[4] = {0.f, 0.f, 0.f, 0.f};
            float* po = out + (size_t)b * HID + h;

            #pragma unroll 1
            for (int t = 0; t < T_STEPS; t += 8) {
                float yin[8];
                #pragma unroll
                for (int u = 0; u < 8; ++u)
                    yin[u] = xs[(t + u) * XP + st] + bias_h;

                #pragma unroll
                for (int u = 0; u < 8; ++u) {
                    float y  = yin[u];
                    float sc = 0.f;
                    #pragma unroll
                    for (int l = 0; l < 4; ++l) {
                        const float cch = y * 0.5f;      // exact
                        float vv   = v[l];
                        float accv = 0.f, accs = 0.f;
                        #pragma unroll
                        for (int s = 0; s < 4; ++s) {
                            vv = __fmaf_rn(vv, 0.5f, cch);       // charge
                            const float sp = (vv >= 1.0f) ? 1.0f : 0.0f;
                            vv -= sp;                             // soft reset
                            accv += vv;
                            accs += sp;
                        }
                        v[l]  = vv;
                        y     = accv * 0.25f;
                        av[l] = y;
                        sc    = accs * 0.25f;
                    }
                    po[(size_t)(t + u) * BH] = sc;
                }
            }
            #pragma unroll
            for (int l = 0; l < 4; ++l)
                states[(size_t)l * BH + (size_t)b * HID + h] = av[l];
        }

        if (tile < NTILES) __syncthreads();     // tile handoff (all 512)
    }
}

// ---------------------------------------------------------------------------
// Launch
// ---------------------------------------------------------------------------
extern "C" void kernel_launch(void* const* d_in, const int* in_sizes, int n_in,
                              void* d_out, int out_size)
{
    const float* x = (const float*)d_in[0];   // [T, B, INP]
    const float* W = (const float*)d_in[1];   // [HID, INP]
    const float* b = (const float*)d_in[2];   // [HID]

    float* out    = (float*)d_out;                    // [T, B, H]
    float* states = out + (size_t)T_STEPS * BH;       // [4, B, H]

    // 1) merged split pass (x + W)
    split_kernel<<<XBLK + WBLK, 256>>>((const float4*)x, (const float4*)W);

    // 2) fused pipelined GEMM + scan
    cudaFuncSetAttribute(fused_kernel,
                         cudaFuncAttributeMaxDynamicSharedMemorySize, SMEM_TOTAL);
    fused_kernel<<<BATCH, NTH, SMEM_TOTAL>>>(b, out, states);
}

// round 17
// speedup vs baseline: 1.3468x; 1.3468x over previous
#include <cuda_runtime.h>
#include <cuda_fp16.h>
#include <cstdint>

// ---------------------------------------------------------------------------
// Problem constants
// ---------------------------------------------------------------------------
namespace {
constexpr int T_STEPS = 128, BATCH = 512, HID = 512, INP = 512;
constexpr int M_TOT = T_STEPS * BATCH;              // 65536 rows
constexpr long long BH = (long long)BATCH * HID;    // 262144 sequences

// Fused kernel tiling: CTA = (all 128 t) x (256 h), BK=16, warp tile 64x64
constexpr int BM = 128, BN = 256, BK = 16;
constexpr int CHUNKS = INP / BK;                    // 32
constexpr int PITCH  = 48;                          // 32B data + 16B pad (bank-clean)
constexpr int A_T    = BM * PITCH;                  // 6144  per A split
constexpr int B_T    = BN * PITCH;                  // 12288 per B split
constexpr int OFF_AH = 0;
constexpr int OFF_AM = A_T;
constexpr int OFF_BH = 2 * A_T;
constexpr int OFF_BM = 2 * A_T + B_T;
constexpr int STAGE_B = 2 * A_T + 2 * B_T;          // 36864
constexpr int NSTAGE = 4;
constexpr int SMEM_TOTAL = NSTAGE * STAGE_B;        // 147456, 1 CTA/SM
// xp tile overlays pipeline smem after mainloop: 128 x 256 fp32, pitch 264
constexpr int XP = 264;                             // 128*264*4 = 135168 <= 147456
// split grid partition
constexpr int XBLK = 4096;                          // x: 33554432/32/256
constexpr int WBLK = 32;                            // W: 262144/32/256
}

// Static scratch (allowed; no allocs)
__device__ __half g_xh[(size_t)M_TOT * INP];        // x hi split, [B][T][K] transposed
__device__ __half g_xm[(size_t)M_TOT * INP];        // x mid split, [B][T][K]
__device__ __half g_wh[(size_t)HID * INP];          // [H][K]
__device__ __half g_wm[(size_t)HID * INP];

// ---------------------------------------------------------------------------
// PTX helpers
// ---------------------------------------------------------------------------
__device__ __forceinline__ uint32_t smem_u32(const void* p) {
    uint32_t a;
    asm("{ .reg .u64 t; cvta.to.shared.u64 t, %1; cvt.u32.u64 %0, t; }"
        : "=r"(a) : "l"(p));
    return a;
}
__device__ __forceinline__ void ldsm_x4(uint32_t* r, uint32_t addr) {
    asm volatile("ldmatrix.sync.aligned.m8n8.x4.shared.b16 {%0,%1,%2,%3}, [%4];"
                 : "=r"(r[0]), "=r"(r[1]), "=r"(r[2]), "=r"(r[3]) : "r"(addr));
}
__device__ __forceinline__ void mma_f16(float* c, const uint32_t* a,
                                        const uint32_t* b) {
    asm volatile(
        "mma.sync.aligned.m16n8k16.row.col.f32.f16.f16.f32 "
        "{%0,%1,%2,%3}, {%4,%5,%6,%7}, {%8,%9}, {%0,%1,%2,%3};"
        : "+f"(c[0]), "+f"(c[1]), "+f"(c[2]), "+f"(c[3])
        : "r"(a[0]), "r"(a[1]), "r"(a[2]), "r"(a[3]), "r"(b[0]), "r"(b[1]));
}
__device__ __forceinline__ void cp16(uint32_t dst, const void* src) {
    asm volatile("cp.async.cg.shared.global [%0], [%1], 16;"
                 :: "r"(dst), "l"(src) : "memory");
}
__device__ __forceinline__ void cp_commit() {
    asm volatile("cp.async.commit_group;" ::: "memory");
}
__device__ __forceinline__ void cp_wait2() {
    asm volatile("cp.async.wait_group 2;" ::: "memory");
}
__device__ __forceinline__ uint32_t hpack(__half a, __half b) {
    __half2 t(a, b);
    return *reinterpret_cast<uint32_t*>(&t);
}

// ---------------------------------------------------------------------------
// Merged split pass (R9-proven): 8 float4 per thread.
// Blocks [0, XBLK): x fp32 [T,B,K] -> (hi, mid) fp16 in TRANSPOSED [B,T,K].
// Blocks [XBLK, XBLK+WBLK): W fp32 [H,K] -> (hi, mid) fp16.
// ---------------------------------------------------------------------------
__global__ __launch_bounds__(256)
void split_kernel(const float4* __restrict__ x, const float4* __restrict__ W)
{
    __half hh[4], mm[4];
    if (blockIdx.x < XBLK) {
        const long long gid  = (long long)blockIdx.x * blockDim.x + threadIdx.x;
        const long long flat = gid * 32;                 // element index in [T,B,K]
        const int k0 = (int)(flat & 511);
        const int b  = (int)((flat >> 9) & 511);
        const int t  = (int)(flat >> 18);
        const long long dflat = (((long long)b * T_STEPS + t) << 9) | k0;

        float4 v[8];
        #pragma unroll
        for (int g = 0; g < 8; ++g) v[g] = x[flat / 4 + g];   // MLP 8

        uint32_t hp[16], mp[16];
        #pragma unroll
        for (int g = 0; g < 8; ++g) {
            const float f[4] = {v[g].x, v[g].y, v[g].z, v[g].w};
            #pragma unroll
            for (int j = 0; j < 4; ++j) {
                hh[j] = __float2half_rn(f[j]);
                mm[j] = __float2half_rn(f[j] - __half2float(hh[j]));
            }
            hp[g * 2 + 0] = hpack(hh[0], hh[1]); hp[g * 2 + 1] = hpack(hh[2], hh[3]);
            mp[g * 2 + 0] = hpack(mm[0], mm[1]); mp[g * 2 + 1] = hpack(mm[2], mm[3]);
        }
        uint4* hd = (uint4*)g_xh;
        uint4* md = (uint4*)g_xm;
        const long long o = dflat / 8;                   // uint4 = 8 halves
        #pragma unroll
        for (int g = 0; g < 4; ++g) {
            hd[o + g] = make_uint4(hp[4 * g], hp[4 * g + 1], hp[4 * g + 2], hp[4 * g + 3]);
            md[o + g] = make_uint4(mp[4 * g], mp[4 * g + 1], mp[4 * g + 2], mp[4 * g + 3]);
        }
    } else {
        const int i = (((int)blockIdx.x - XBLK) * 256 + (int)threadIdx.x) * 8;
        float4 v[8];
        #pragma unroll
        for (int g = 0; g < 8; ++g) v[g] = W[i + g];
        uint32_t hp[16], mp[16];
        #pragma unroll
        for (int g = 0; g < 8; ++g) {
            const float f[4] = {v[g].x, v[g].y, v[g].z, v[g].w};
            #pragma unroll
            for (int j = 0; j < 4; ++j) {
                hh[j] = __float2half_rn(f[j]);
                mm[j] = __float2half_rn(f[j] - __half2float(hh[j]));
            }
            hp[g * 2 + 0] = hpack(hh[0], hh[1]); hp[g * 2 + 1] = hpack(hh[2], hh[3]);
            mp[g * 2 + 0] = hpack(mm[0], mm[1]); mp[g * 2 + 1] = hpack(mm[2], mm[3]);
        }
        uint4* hd = (uint4*)g_wh;
        uint4* md = (uint4*)g_wm;
        const int o = i / 2;
        #pragma unroll
        for (int g = 0; g < 4; ++g) {
            hd[o + g] = make_uint4(hp[4 * g], hp[4 * g + 1], hp[4 * g + 2], hp[4 * g + 3]);
            md[o + g] = make_uint4(mp[4 * g], mp[4 * g + 1], mp[4 * g + 2], mp[4 * g + 3]);
        }
    }
}

// ---------------------------------------------------------------------------
// FUSED kernel (R9 champion), CTA = (hblk of 256, batch b):
//   1) HMMA GEMM xp[t, h] = sum_k x[t,b,k]*W[h,k]  (3 fp16 terms hh+hm+mh)
//   2) acc -> smem xp tile (fp32, pitch 264 words)
//   3) all 256 threads: LIF scan over t from smem (bias added on read).
// ---------------------------------------------------------------------------
__global__ __launch_bounds__(256, 1)
void fused_kernel(const float* __restrict__ bias,
                  float* __restrict__ out, float* __restrict__ states)
{
    extern __shared__ char smem[];
    const uint32_t sbase = smem_u32(smem);
    const int tid = threadIdx.x;
    const int wid = tid >> 5;
    const int lid = tid & 31;
    const int n0 = blockIdx.x * BN;                  // h block (0 or 256)
    const int b  = blockIdx.y;                       // batch

    const __half* Ah = g_xh + (size_t)b * T_STEPS * INP;   // [T][K] for batch b
    const __half* Am = g_xm + (size_t)b * T_STEPS * INP;

    const int warp_m = wid & 1;          // 64-row (t) half
    const int warp_n = wid >> 1;         // 64-col (h) slice

    const int quad = lid >> 3, lrow = lid & 7;
    const uint32_t laneA = (uint32_t)(((quad & 1) * 8 + lrow) * PITCH + (quad >> 1) * 16);
    const uint32_t laneB = (uint32_t)(((quad >> 1) * 8 + lrow) * PITCH + (quad & 1) * 16);

    float acc[4][8][4];
    #pragma unroll
    for (int i = 0; i < 4; ++i)
        #pragma unroll
        for (int j = 0; j < 8; ++j)
            #pragma unroll
            for (int k = 0; k < 4; ++k) acc[i][j][k] = 0.f;

    // stage fill: 1536 x 16B chunks, 6/thread
    auto issue_stage = [&](int c) {
        const int kt = c * BK;
        const uint32_t sdst = sbase + (uint32_t)((c & 3) * STAGE_B);
        #pragma unroll
        for (int i = 0; i < 6; ++i) {
            const int q = i * 256 + tid;
            const __half* src;
            uint32_t dst;
            if (i == 0) {
                const int row = q >> 1, cc = q & 1;
                src = Ah + (size_t)row * INP + kt + cc * 8;
                dst = (uint32_t)(OFF_AH + row * PITCH + cc * 16);
            } else if (i == 1) {
                const int t = q - 256, row = t >> 1, cc = t & 1;
                src = Am + (size_t)row * INP + kt + cc * 8;
                dst = (uint32_t)(OFF_AM + row * PITCH + cc * 16);
            } else if (i < 4) {
                const int t = q - 512, row = t >> 1, cc = t & 1;
                src = g_wh + (size_t)(n0 + row) * INP + kt + cc * 8;
                dst = (uint32_t)(OFF_BH + row * PITCH + cc * 16);
            } else {
                const int t = q - 1024, row = t >> 1, cc = t & 1;
                src = g_wm + (size_t)(n0 + row) * INP + kt + cc * 8;
                dst = (uint32_t)(OFF_BM + row * PITCH + cc * 16);
            }
            cp16(sdst + dst, src);
        }
        cp_commit();
    };

    issue_stage(0);
    issue_stage(1);
    issue_stage(2);

    for (int c = 0; c < CHUNKS; ++c) {
        cp_wait2();
        __syncthreads();

        const uint32_t stg = sbase + (uint32_t)((c & 3) * STAGE_B);
        const uint32_t aB  = stg + (uint32_t)(warp_m * 64 * PITCH) + laneA;
        const uint32_t bB  = stg + (uint32_t)(warp_n * 64 * PITCH) + laneB;

        uint32_t afr[4][4], bfh[8][2], bfm[8][2];

        #pragma unroll
        for (int bp = 0; bp < 4; ++bp) {
            uint32_t r4[4];
            ldsm_x4(r4, bB + (uint32_t)(OFF_BH + bp * 16 * PITCH));
            bfh[bp * 2 + 0][0] = r4[0]; bfh[bp * 2 + 0][1] = r4[1];
            bfh[bp * 2 + 1][0] = r4[2]; bfh[bp * 2 + 1][1] = r4[3];
            ldsm_x4(r4, bB + (uint32_t)(OFF_BM + bp * 16 * PITCH));
            bfm[bp * 2 + 0][0] = r4[0]; bfm[bp * 2 + 0][1] = r4[1];
            bfm[bp * 2 + 1][0] = r4[2]; bfm[bp * 2 + 1][1] = r4[3];
        }
        #pragma unroll
        for (int mt = 0; mt < 4; ++mt)
            ldsm_x4(afr[mt], aB + (uint32_t)(OFF_AH + mt * 16 * PITCH));

        if (c + 3 < CHUNKS) issue_stage(c + 3);
        else                cp_commit();

        // hh + hm
        #pragma unroll
        for (int mt = 0; mt < 4; ++mt)
            #pragma unroll
            for (int nt = 0; nt < 8; ++nt)
                mma_f16(acc[mt][nt], afr[mt], bfh[nt]);
        #pragma unroll
        for (int mt = 0; mt < 4; ++mt)
            #pragma unroll
            for (int nt = 0; nt < 8; ++nt)
                mma_f16(acc[mt][nt], afr[mt], bfm[nt]);

        // mh
        #pragma unroll
        for (int mt = 0; mt < 4; ++mt)
            ldsm_x4(afr[mt], aB + (uint32_t)(OFF_AM + mt * 16 * PITCH));
        #pragma unroll
        for (int mt = 0; mt < 4; ++mt)
            #pragma unroll
            for (int nt = 0; nt < 8; ++nt)
                mma_f16(acc[mt][nt], afr[mt], bfh[nt]);
    }

    // ---- stage 2: acc -> smem xp tile (overlays pipeline buffers) ----
    __syncthreads();
    float* xs = (float*)smem;              // [128][XP]
    const int tr = lid >> 2;
    const int tc = (lid & 3) * 2;
    #pragma unroll
    for (int nt = 0; nt < 8; ++nt) {
        const int col = warp_n * 64 + nt * 8 + tc;
        #pragma unroll
        for (int mt = 0; mt < 4; ++mt) {
            const int row = warp_m * 64 + mt * 16 + tr;
            *(float2*)&xs[row * XP + col]       = make_float2(acc[mt][nt][0], acc[mt][nt][1]);
            *(float2*)&xs[(row + 8) * XP + col] = make_float2(acc[mt][nt][2], acc[mt][nt][3]);
        }
    }
    __syncthreads();

    // ---- stage 3: LIF scan from smem (all 256 threads, one per h column) ----
    {
        const int h = n0 + tid;
        const float bias_h = bias[h];

        float v[4]  = {0.f, 0.f, 0.f, 0.f};
        float av[4] = {0.f, 0.f, 0.f, 0.f};

        float* po = out + (size_t)b * HID + h;

        #pragma unroll 1
        for (int t = 0; t < T_STEPS; t += 8) {
            float yin[8];
            #pragma unroll
            for (int u = 0; u < 8; ++u)
                yin[u] = xs[(t + u) * XP + tid] + bias_h;

            #pragma unroll
            for (int u = 0; u < 8; ++u) {
                float y  = yin[u];
                float sc = 0.f;
                #pragma unroll
                for (int l = 0; l < 4; ++l) {
                    const float cch = y * 0.5f;          // exact
                    float vv   = v[l];
                    float accv = 0.f, accs = 0.f;
                    #pragma unroll
                    for (int s = 0; s < 4; ++s) {
                        vv = __fmaf_rn(vv, 0.5f, cch);           // charge
                        const float sp = (vv >= 1.0f) ? 1.0f : 0.0f;
                        vv -= sp;                                 // soft reset
                        accv += vv;
                        accs += sp;
                    }
                    v[l]  = vv;
                    y     = accv * 0.25f;
                    av[l] = y;
                    sc    = accs * 0.25f;
                }
                po[(size_t)(t + u) * BH] = sc;
            }
        }

        #pragma unroll
        for (int l = 0; l < 4; ++l)
            states[(size_t)l * BH + (size_t)b * HID + h] = av[l];
    }
}

// ---------------------------------------------------------------------------
// Launch
// ---------------------------------------------------------------------------
extern "C" void kernel_launch(void* const* d_in, const int* in_sizes, int n_in,
                              void* d_out, int out_size)
{
    const float* x = (const float*)d_in[0];   // [T, B, INP]
    const float* W = (const float*)d_in[1];   // [HID, INP]
    const float* b = (const float*)d_in[2];   // [HID]

    float* out    = (float*)d_out;                    // [T, B, H]
    float* states = out + (size_t)T_STEPS * BH;       // [4, B, H]

    // 1) merged split pass (x + W)
    split_kernel<<<XBLK + WBLK, 256>>>((const float4*)x, (const float4*)W);

    // 2) fused GEMM + scan
    cudaFuncSetAttribute(fused_kernel,
                         cudaFuncAttributeMaxDynamicSharedMemorySize, SMEM_TOTAL);
    dim3 grid(HID / BN, BATCH);                       // (2, 512)
    fused_kernel<<<grid, 256, SMEM_TOTAL>>>(b, out, states);
}